// round 5
// baseline (speedup 1.0000x reference)
#include <cuda_runtime.h>
#include <cstdint>

#define THREADS 256
#define ROW_LEN 16384
#define KSEL 64
#define SEG 12                       // per-thread candidate slots
#define CAP (THREADS * SEG)          // 3072 words scanned by radix
#define CAND_WORDS (THREADS * 13)    // + 256-word pad (absorbs overflow spray)
#define T0F 2.30f                    // filter; exact fallback covers any input

// Monotonic transform (only used for winners + fallback path).
__device__ __forceinline__ uint32_t fwd_xform(uint32_t u) {
    return (u & 0x80000000u) ? ~u : (u | 0x80000000u);
}
__device__ __forceinline__ float inv_xform(uint32_t u) {
    return __uint_as_float((u & 0x80000000u) ? (u ^ 0x80000000u) : ~u);
}

__device__ __forceinline__ uint32_t smem_u32(const void* p) {
    uint32_t a;
    asm("{ .reg .u64 t; cvta.to.shared.u64 t, %1; cvt.u32.u64 %0, t; }"
        : "=r"(a) : "l"(p));
    return a;
}

// Branch-free predicated push: FSETP + @P STS + @P IADD. No BSSY, no atomics.
// addr is the running store cursor (doubles as the per-thread counter).
__device__ __forceinline__ void push(float f, uint32_t& addr) {
    asm volatile(
        "{\n\t"
        ".reg .pred p;\n\t"
        "setp.gt.f32 p, %1, %2;\n\t"
        "@p st.shared.b32 [%0], %3;\n\t"
        "@p add.u32 %0, %0, 4;\n\t"
        "}"
        : "+r"(addr)
        : "f"(f), "f"(T0F), "r"(__float_as_uint(f))
        : "memory");
}

// Warp-aggregated histogram add (small candidate set only).
__device__ __forceinline__ void hist_add(uint32_t* hist, uint32_t digit,
                                         bool active, int lane) {
    uint32_t key = active ? digit : (0x1000u | (uint32_t)lane);
    unsigned m = __match_any_sync(0xFFFFFFFFu, key);
    if (active && lane == (__ffs(m) - 1))
        atomicAdd(&hist[digit], (uint32_t)__popc(m));
}

__global__ void __launch_bounds__(THREADS, 4)
topk64_kernel(const float* __restrict__ x, float* __restrict__ out) {
    __shared__ uint32_t cand[CAND_WORDS];   // slots + pad; raw positive-float bits
    __shared__ uint32_t hist[256];
    __shared__ uint32_t sel[KSEL];          // transformed domain
    __shared__ uint32_t wsum[THREADS / 32];
    __shared__ uint32_t misc[4];  // [0]=fb flag, [1]=radix prefix, [2]=krem, [3]=sel cnt

    const int row  = blockIdx.x;
    const int tid  = threadIdx.x;
    const int lane = tid & 31;
    const int wid  = tid >> 5;

    const uint32_t* src  = reinterpret_cast<const uint32_t*>(x) + (size_t)row * ROW_LEN;
    const float4*   src4 = reinterpret_cast<const float4*>(src);

    // Zero-fill candidate buffer (filler 0 = smallest; can't reach top-64).
    #pragma unroll
    for (int i = 0; i < 13; ++i) cand[i * THREADS + tid] = 0;
    __syncthreads();

    const uint32_t base_addr = smem_u32(cand) + (uint32_t)tid * (SEG * 4);
    uint32_t addr = base_addr;

    // ---- Phase 1: single global pass, front-batched loads, branchless filter ----
    #pragma unroll
    for (int ot = 0; ot < 2; ++ot) {
        float4 v[8];
        #pragma unroll
        for (int j = 0; j < 8; ++j)
            v[j] = src4[(ot * 8 + j) * THREADS + tid];
        #pragma unroll
        for (int j = 0; j < 8; ++j) {
            push(v[j].x, addr);
            push(v[j].y, addr);
            push(v[j].z, addr);
            push(v[j].w, addr);
        }
    }

    // ---- Fallback check: any per-thread overflow, or fewer than 64 total ----
    const uint32_t cnt = (addr - base_addr) >> 2;
    hist[tid] = 0;
    if (tid == 0) { misc[1] = 0; misc[2] = KSEL; misc[3] = 0; }
    const uint32_t wtot = __reduce_add_sync(0xFFFFFFFFu, cnt);
    if (lane == 0) wsum[wid] = wtot;
    const int novf = __syncthreads_count((int)(cnt > SEG));  // barrier: covers all above
    if (tid == 0) {
        uint32_t total = 0;
        #pragma unroll
        for (int w = 0; w < THREADS / 32; ++w) total += wsum[w];
        misc[0] = (novf > 0) || (total < KSEL);
    }
    __syncthreads();
    const bool fb = (misc[0] != 0);

    uint32_t T;  // transformed-domain bit pattern of the 64th largest

    if (!fb) {
        // ---- Phase 2: exact radix-select over raw bits (all positive or 0) ----
        #pragma unroll
        for (int i = 0; i < SEG; ++i)
            hist_add(hist, cand[i * THREADS + tid] >> 24, true, lane);
        __syncthreads();

        #pragma unroll 1
        for (int pass = 0; pass < 4; ++pass) {
            const int shift = 24 - 8 * pass;
            if (tid < 32) {  // warp 0: suffix-scan digit find over 256 bins
                uint32_t h[8]; uint32_t t = 0;
                #pragma unroll
                for (int j = 0; j < 8; ++j) { h[j] = hist[tid * 8 + j]; t += h[j]; }
                uint32_t s = t;
                #pragma unroll
                for (int off = 1; off < 32; off <<= 1) {
                    uint32_t vv = __shfl_down_sync(0xFFFFFFFFu, s, off);
                    if (tid + off < 32) s += vv;
                }
                const uint32_t krem = misc[2];
                uint32_t c = s - t;
                #pragma unroll
                for (int j = 7; j >= 0; --j) {
                    uint32_t nc = c + h[j];
                    if (nc >= krem && c < krem) {
                        misc[1] |= (uint32_t)(tid * 8 + j) << shift;
                        misc[2] = krem - c;
                    }
                    c = nc;
                }
            }
            __syncthreads();
            if (pass == 3) break;

            hist[tid] = 0;
            const uint32_t prefix = misc[1];
            __syncthreads();

            const int nshift = shift - 8;
            const uint32_t mask = ~((1u << shift) - 1u);
            #pragma unroll
            for (int i = 0; i < SEG; ++i) {
                uint32_t u = cand[i * THREADS + tid];
                hist_add(hist, (u >> nshift) & 255u, (u & mask) == prefix, lane);
            }
            __syncthreads();
        }
        const uint32_t Traw = misc[1];
        T = Traw | 0x80000000u;  // positive raw -> transformed

        // Compact strict survivors (> Traw); exactly KSEL - krem <= 63 of them.
        #pragma unroll
        for (int i = 0; i < SEG; ++i) {
            uint32_t u = cand[i * THREADS + tid];
            if (u > Traw) {
                uint32_t pos = atomicAdd(&misc[3], 1u);
                if (pos < KSEL) sel[pos] = u | 0x80000000u;
            }
        }
    } else {
        // ---- Fallback (exact, any input): bitwise search over the full row ----
        T = 0;
        #pragma unroll 1
        for (int b = 31; b >= 0; --b) {
            uint32_t c = T | (1u << b);
            int loc = 0;
            for (int i = tid; i < ROW_LEN; i += THREADS)
                loc += (int)(fwd_xform(src[i]) >= c);
            int wsumc = __reduce_add_sync(0xFFFFFFFFu, loc);
            if (tid == 0) misc[3] = 0;
            __syncthreads();
            if (lane == 0) atomicAdd(&misc[3], (uint32_t)wsumc);
            __syncthreads();
            if (misc[3] >= KSEL) T = c;
            __syncthreads();
        }
        if (tid == 0) misc[3] = 0;
        __syncthreads();
        for (int i = tid; i < ROW_LEN; i += THREADS) {
            uint32_t u = fwd_xform(src[i]);
            if (u > T) {
                uint32_t pos = atomicAdd(&misc[3], 1u);
                if (pos < KSEL) sel[pos] = u;
            }
        }
    }

    __syncthreads();
    const uint32_t cgt = misc[3];
    if (tid >= (int)cgt && tid < KSEL) sel[tid] = T;  // tie fill
    __syncthreads();

    // ---- Phase 3: rank-sort the 64 winners (descending), write ----
    if (tid < KSEL) {
        uint32_t v = sel[tid];
        int rank = 0;
        #pragma unroll
        for (int j = 0; j < KSEL; ++j) {
            uint32_t u = sel[j];
            rank += (int)((u > v) | ((u == v) & (j < tid)));
        }
        out[(size_t)row * KSEL + rank] = inv_xform(v);
    }
}

extern "C" void kernel_launch(void* const* d_in, const int* in_sizes, int n_in,
                              void* d_out, int out_size) {
    const float* x = (const float*)d_in[0];
    float* out = (float*)d_out;
    int rows = in_sizes[0] / ROW_LEN;  // 8192
    topk64_kernel<<<rows, THREADS>>>(x, out);
}